// round 17
// baseline (speedup 1.0000x reference)
#include <cuda_runtime.h>
#include <cstdint>

// Find_Ring_Bonds: B=16384 molecules, A=80 atoms, D=4 neighbors, R=10 rings, S=8.
// edges: [B, A, D] float32 (integer-valued, -1 = null neighbor)
// rings: [B, R, S] int32 (-1 = padding)
// out:   [B, A, D] float32 (1.0 iff bond (a, e[a][d]) lies in some ring)
//
// Warp-private (R16) + TMA bulk output store. Five structural variants all
// pinned at 10.72us; the remaining un-varied resource is the LSU cycle
// budget, whose largest single item is the output STG.128 stream (~30
// LSU-cyc/molecule). Here results are staged into shared (overlaying the
// dead 1280B 'staging' buffer) and written out with one
// cp.async.bulk.global.shared::cta per warp — the TMA engine carries the
// 20 MB output stream instead of the LSU.
//
// Ring membership: R12 RMW-free byte scatter (16 flag bytes/atom, plain byte
// STS — per-lane byte enables, no RMW hazard), collapsed to a 10-bit mask via
// movemask multiplies (ring bit order permuted but consistent; masks only
// ever ANDed against each other).

static constexpr int A = 80;
static constexpr int D = 4;
static constexpr int R = 10;
static constexpr int S = 8;
static constexpr int WARPS_PER_BLOCK = 8;
static constexpr int THREADS = WARPS_PER_BLOCK * 32;   // 256
static constexpr int MOL_OUT_BYTES = A * D * 4;        // 1280 B per molecule

__global__ __launch_bounds__(THREADS, 8)
void find_ring_bonds_kernel(const float* __restrict__ edges,
                            const int*   __restrict__ rings,
                            float*       __restrict__ out,
                            int batch)
{
    // staging: 16 flag bytes per atom during the scatter phase; after the
    // collapse it is dead and is reused as the 1280-byte output tile.
    __shared__ uint4        staging[WARPS_PER_BLOCK][A];
    __shared__ unsigned int masks[WARPS_PER_BLOCK][A];

    const int w    = threadIdx.x >> 5;     // warp in block -> molecule owner
    const int lane = threadIdx.x & 31;
    const int mol  = blockIdx.x * WARPS_PER_BLOCK + w;
    if (mol >= batch) return;              // warp-uniform exit

    const float4* E  = reinterpret_cast<const float4*>(edges) + (long)mol * A;
    const int4*   Rv = reinterpret_cast<const int4*>(rings) + (long)mol * (R * S / 4);

    // ---- Front-batch all global loads for this molecule.
    const float4 ea0 = E[lane];                       // atoms 0..31
    const float4 ea1 = E[32 + lane];                  // atoms 32..63
    float4 ea2 = make_float4(-1.f, -1.f, -1.f, -1.f); // atoms 64..79
    if (lane < A - 64) ea2 = E[64 + lane];
    int4 rv = make_int4(-1, -1, -1, -1);
    if (lane < (R * S / 4)) rv = Rv[lane];            // 4 ring entries / lane

    // ---- Zero staging rows (one STS.128 per owned atom).
    const uint4 z = make_uint4(0u, 0u, 0u, 0u);
    staging[w][lane]      = z;
    staging[w][32 + lane] = z;
    if (lane < A - 64) staging[w][64 + lane] = z;
    __syncwarp();

    // ---- RMW-free byte scatter: lane l owns ring entries 4l..4l+3.
    if (lane < (R * S / 4)) {
        const int base = lane * 4;
        const int v0 = rv.x, v1 = rv.y, v2 = rv.z, v3 = rv.w;
        if (v0 >= 0) reinterpret_cast<char*>(&staging[w][v0])[(base + 0) >> 3] = 1;
        if (v1 >= 0) reinterpret_cast<char*>(&staging[w][v1])[(base + 1) >> 3] = 1;
        if (v2 >= 0) reinterpret_cast<char*>(&staging[w][v2])[(base + 2) >> 3] = 1;
        if (v3 >= 0) reinterpret_cast<char*>(&staging[w][v3])[(base + 3) >> 3] = 1;
    }
    __syncwarp();

    // ---- Collapse staging rows into 10-bit masks (movemask multiplies).
    const unsigned int M = 0x08040201u;
    unsigned int mk0, mk1, mk2 = 0u;
    {
        const uint4 r0 = staging[w][lane];
        mk0 = ((r0.x * M) >> 24 & 0xFu) | (((r0.y * M) >> 24 & 0xFu) << 4)
            | (((r0.z * M) >> 24 & 0xFu) << 8);
        masks[w][lane] = mk0;

        const uint4 r1 = staging[w][32 + lane];
        mk1 = ((r1.x * M) >> 24 & 0xFu) | (((r1.y * M) >> 24 & 0xFu) << 4)
            | (((r1.z * M) >> 24 & 0xFu) << 8);
        masks[w][32 + lane] = mk1;

        if (lane < A - 64) {
            const uint4 r2 = staging[w][64 + lane];
            mk2 = ((r2.x * M) >> 24 & 0xFu) | (((r2.y * M) >> 24 & 0xFu) << 4)
                | (((r2.z * M) >> 24 & 0xFu) << 8);
            masks[w][64 + lane] = mk2;
        }
    }
    __syncwarp();   // masks[] complete; staging now dead -> reuse as out tile

    // ---- Resolve neighbor slots; stage results into the (dead) staging rows.
    float4* res = reinterpret_cast<float4*>(&staging[w][0]);
    {
        const int e0 = (int)ea0.x, e1 = (int)ea0.y, e2 = (int)ea0.z, e3 = (int)ea0.w;
        float4 o;
        o.x = (e0 >= 0 && (mk0 & masks[w][e0])) ? 1.0f : 0.0f;
        o.y = (e1 >= 0 && (mk0 & masks[w][e1])) ? 1.0f : 0.0f;
        o.z = (e2 >= 0 && (mk0 & masks[w][e2])) ? 1.0f : 0.0f;
        o.w = (e3 >= 0 && (mk0 & masks[w][e3])) ? 1.0f : 0.0f;
        res[lane] = o;
    }
    {
        const int e0 = (int)ea1.x, e1 = (int)ea1.y, e2 = (int)ea1.z, e3 = (int)ea1.w;
        float4 o;
        o.x = (e0 >= 0 && (mk1 & masks[w][e0])) ? 1.0f : 0.0f;
        o.y = (e1 >= 0 && (mk1 & masks[w][e1])) ? 1.0f : 0.0f;
        o.z = (e2 >= 0 && (mk1 & masks[w][e2])) ? 1.0f : 0.0f;
        o.w = (e3 >= 0 && (mk1 & masks[w][e3])) ? 1.0f : 0.0f;
        res[32 + lane] = o;
    }
    if (lane < A - 64) {
        const int e0 = (int)ea2.x, e1 = (int)ea2.y, e2 = (int)ea2.z, e3 = (int)ea2.w;
        float4 o;
        o.x = (e0 >= 0 && (mk2 & masks[w][e0])) ? 1.0f : 0.0f;
        o.y = (e1 >= 0 && (mk2 & masks[w][e1])) ? 1.0f : 0.0f;
        o.z = (e2 >= 0 && (mk2 & masks[w][e2])) ? 1.0f : 0.0f;
        o.w = (e3 >= 0 && (mk2 & masks[w][e3])) ? 1.0f : 0.0f;
        res[64 + lane] = o;
    }
    __syncwarp();

    // ---- One TMA bulk store per warp: shared (1280B tile) -> global.
    if (lane == 0) {
        asm volatile("fence.proxy.async.shared::cta;" ::: "memory");
        uint32_t src;
        asm("{ .reg .u64 t; cvta.to.shared.u64 t, %1; cvt.u32.u64 %0, t; }"
            : "=r"(src) : "l"((const void*)&staging[w][0]));
        const char* dst = reinterpret_cast<const char*>(out) + (long)mol * MOL_OUT_BYTES;
        asm volatile("cp.async.bulk.global.shared::cta.bulk_group [%0], [%1], %2;"
                     :: "l"(dst), "r"(src), "r"((int)MOL_OUT_BYTES) : "memory");
        asm volatile("cp.async.bulk.commit_group;" ::: "memory");
        asm volatile("cp.async.bulk.wait_group 0;" ::: "memory");
    }
}

extern "C" void kernel_launch(void* const* d_in, const int* in_sizes, int n_in,
                              void* d_out, int out_size)
{
    const float* edges = (const float*)d_in[0];   // [B, A, D] float32
    const int*   rings = (const int*)d_in[1];     // [B, R, S] int32
    float* out = (float*)d_out;                   // [B, A, D, 1] float32

    const int batch = out_size / (A * D);                             // 16384
    const int grid = (batch + WARPS_PER_BLOCK - 1) / WARPS_PER_BLOCK; // 2048

    find_ring_bonds_kernel<<<grid, THREADS>>>(edges, rings, out, batch);
}